// round 5
// baseline (speedup 1.0000x reference)
#include <cuda_runtime.h>
#include <cuda_bf16.h>
#include <stdint.h>
#include <math.h>

// Shapes (fixed): x [32, 512, 2048] f32, codebook [1024, 512] f32.
#define NB 32
#define CD 512
#define TD 2048
#define KC 1024
#define NT_ROWS (NB * TD)
#define XD_ELEMS ((long long)NB * CD * TD)

#define ROWS_PER_CTA 128
#define N_SCREEN_CTAS (NT_ROWS / ROWS_PER_CTA)   // 512

// smem layout (bytes) for the screen kernel
#define A_STRIDE_W 260            // (512+8) bf16 = 260 words/row; 1040B = 65*16B
#define B_STRIDE_W 36             // (64+8) bf16 = 36 words/row; 144B = 9*16B
#define SM_AS 0                   // A: 128*260*4 = 133120
#define SM_BS 133120              // B: two 18432-byte buffers
#define BBUF 18432
#define SM_TV (SM_BS + 2 * BBUF)  // 169984 : top-4 vals 32*256*4 = 32768
#define SM_TI (SM_TV + 32768)     // 202752 : top-4 idx (u16) 32*256*2 = 16384
#define SM_TOTAL (SM_TI + 16384)  // 219136
// merge scratch reuses the B region (16 KB needed, 36 KB available)
#define SM_MV SM_BS
#define SM_MI (SM_BS + 8192)

// ---- global scratch (no cudaMalloc allowed) ----
__device__ __align__(16) __nv_bfloat16 g_cb_bf16[KC * CD];   // 1 MB
__device__ float g_half_hat[KC];      // 0.5*||bf16(c)||^2 (screen-consistent)
__device__ float g_half_exact[KC];    // 0.5*||c||^2 fp32 (rescore)
__device__ __align__(16) float g_scr_v[NT_ROWS * 4];
__device__ __align__(16) int   g_scr_i[NT_ROWS * 4];

// ===========================================================================
// Kernel 1: codebook prep — bf16 convert + half norms (exact f32 & bf16-hat).
// ===========================================================================
__global__ void vq_prep_kernel(const float* __restrict__ cb)
{
    const int k = blockIdx.x;
    const int tid = threadIdx.x;                    // 128 threads x float4
    const float4 v = reinterpret_cast<const float4*>(cb + (size_t)k * CD)[tid];

    __nv_bfloat162 p01 = __floats2bfloat162_rn(v.x, v.y);
    __nv_bfloat162 p23 = __floats2bfloat162_rn(v.z, v.w);
    uint2 u;
    u.x = *reinterpret_cast<uint32_t*>(&p01);
    u.y = *reinterpret_cast<uint32_t*>(&p23);
    reinterpret_cast<uint2*>(g_cb_bf16)[(size_t)k * (CD / 4) + tid] = u;

    float se = v.x * v.x + v.y * v.y + v.z * v.z + v.w * v.w;
    const float h0 = __bfloat162float(p01.x), h1 = __bfloat162float(p01.y);
    const float h2 = __bfloat162float(p23.x), h3 = __bfloat162float(p23.y);
    float sh = h0 * h0 + h1 * h1 + h2 * h2 + h3 * h3;
#pragma unroll
    for (int o = 16; o > 0; o >>= 1) {
        se += __shfl_xor_sync(0xffffffffu, se, o);
        sh += __shfl_xor_sync(0xffffffffu, sh, o);
    }
    __shared__ float wse[4], wsh[4];
    if ((tid & 31) == 0) { wse[tid >> 5] = se; wsh[tid >> 5] = sh; }
    __syncthreads();
    if (tid == 0) {
        g_half_exact[k] = 0.5f * (wse[0] + wse[1] + wse[2] + wse[3]);
        g_half_hat[k]   = 0.5f * (wsh[0] + wsh[1] + wsh[2] + wsh[3]);
    }
}

// ---------------------------------------------------------------------------
__device__ __forceinline__ void mma16816(float* d, const uint32_t* a,
                                         const uint32_t* b)
{
    asm volatile(
        "mma.sync.aligned.m16n8k16.row.col.f32.bf16.bf16.f32 "
        "{%0,%1,%2,%3}, {%4,%5,%6,%7}, {%8,%9}, {%0,%1,%2,%3};"
        : "+f"(d[0]), "+f"(d[1]), "+f"(d[2]), "+f"(d[3])
        : "r"(a[0]), "r"(a[1]), "r"(a[2]), "r"(a[3]), "r"(b[0]), "r"(b[1]));
}
__device__ __forceinline__ void ldsm_x4(uint32_t* r, uint32_t addr)
{
    asm volatile("ldmatrix.sync.aligned.m8n8.x4.shared.b16 {%0,%1,%2,%3}, [%4];"
                 : "=r"(r[0]), "=r"(r[1]), "=r"(r[2]), "=r"(r[3]) : "r"(addr));
}
__device__ __forceinline__ uint32_t smem_u32(const void* p)
{
    uint32_t a;
    asm("{ .reg .u64 t; cvta.to.shared.u64 t, %1; cvt.u32.u64 %0, t; }"
        : "=r"(a) : "l"(p));
    return a;
}

// sorted-desc insert into a 4-entry smem list (vals f32 [slot*4+j][256], idx u16)
__device__ __forceinline__ void ins4(float* tvs, unsigned short* tis, int tid,
                                     int slot, float v, int idx)
{
    const int b = (slot << 2) * 256 + tid;
    if (v > tvs[b + 768]) {
        const float v0 = tvs[b], v1 = tvs[b + 256], v2 = tvs[b + 512];
        const unsigned short i0 = tis[b], i1 = tis[b + 256], i2 = tis[b + 512];
        if (v > v2) {
            tvs[b + 768] = v2; tis[b + 768] = i2;
            if (v > v1) {
                tvs[b + 512] = v1; tis[b + 512] = i1;
                if (v > v0) {
                    tvs[b + 256] = v0; tis[b + 256] = i0;
                    tvs[b] = v; tis[b] = (unsigned short)idx;
                } else { tvs[b + 256] = v; tis[b + 256] = (unsigned short)idx; }
            } else { tvs[b + 512] = v; tis[b + 512] = (unsigned short)idx; }
        } else { tvs[b + 768] = v; tis[b + 768] = (unsigned short)idx; }
    }
}

// reg-side sorted-desc insert into 4-entry list
__device__ __forceinline__ void rins4(float* v4, int* i4, float v, int idx)
{
    if (v > v4[3]) {
        if (v > v4[2]) {
            v4[3] = v4[2]; i4[3] = i4[2];
            if (v > v4[1]) {
                v4[2] = v4[1]; i4[2] = i4[1];
                if (v > v4[0]) { v4[1] = v4[0]; i4[1] = i4[0]; v4[0] = v; i4[0] = idx; }
                else           { v4[1] = v; i4[1] = idx; }
            } else { v4[2] = v; i4[2] = idx; }
        } else { v4[3] = v; i4[3] = idx; }
    }
}

// ===========================================================================
// Kernel 2: bf16 mma.sync screen with ldmatrix fragments + double-buffered B.
// 512 CTAs x 256 thr (8 warps, 2x4). A (128x512) resident; B streamed in
// 64-wide k-chunks, 2 smem buffers, 1 sync/chunk. Per-lane top-4 in smem.
// ===========================================================================
__global__ __launch_bounds__(256, 1) void vq_screen_kernel(const float* __restrict__ x)
{
    extern __shared__ __align__(16) char smem[];
    uint32_t*       As32 = reinterpret_cast<uint32_t*>(smem + SM_AS);
    float*          tvs  = reinterpret_cast<float*>(smem + SM_TV);
    unsigned short* tis  = reinterpret_cast<unsigned short*>(smem + SM_TI);

    const uint32_t a_base = smem_u32(smem) + SM_AS;
    const uint32_t b_base = smem_u32(smem) + SM_BS;

    const int tid  = threadIdx.x;
    const int lane = tid & 31;
    const int wid  = tid >> 5;
    const int wm   = wid >> 2;          // 0..1  (64 rows each)
    const int wn   = wid & 3;           // 0..3  (32 codes each)
    const int g    = lane >> 2;         // 0..7
    const int t4   = lane & 3;          // 0..3

    // per-lane ldmatrix byte offsets
    // A x4: [m0-7 k0 | m8-15 k0 | m0-7 k8 | m8-15 k8]
    const uint32_t a_lane_off =
        (uint32_t)((((lane & 7) + ((lane >> 3) & 1) * 8) * A_STRIDE_W +
                    (lane >> 4) * 4) * 4);
    // B x4: [c0-7 k0 | c0-7 k8 | c8-15 k0 | c8-15 k8]
    const uint32_t b_lane_off =
        (uint32_t)((((lane & 7) + (lane >> 4) * 8) * B_STRIDE_W +
                    ((lane >> 3) & 1) * 4) * 4);

    const int r0 = blockIdx.x * ROWS_PER_CTA;
    const int n  = r0 >> 11;
    const int t0 = r0 & (TD - 1);

    // ---- stage A: x[n, :, t0..t0+127] -> bf16 smem [row=t][k=c] padded ----
    {
        const int   t   = tid & 127;
        const int   cph = tid >> 7;
        const float* xb = x + (size_t)n * CD * TD + t0 + t;
        for (int cp = cph; cp < 256; cp += 2) {      // cp = c/2
            const float v0 = __ldg(xb + (size_t)(2 * cp) * TD);
            const float v1 = __ldg(xb + (size_t)(2 * cp + 1) * TD);
            __nv_bfloat162 p = __floats2bfloat162_rn(v0, v1);
            As32[t * A_STRIDE_W + cp] = *reinterpret_cast<uint32_t*>(&p);
        }
    }
#pragma unroll
    for (int s = 0; s < 32; ++s) tvs[s * 256 + tid] = -INFINITY;
#pragma unroll
    for (int s = 0; s < 32; ++s) tis[s * 256 + tid] = 0;
    __syncthreads();

    // B staging helpers: idx = tid + i*256 -> code = idx>>3 (0..127), u = idx&7
    uint4 pb[4];
    auto b_fetch = [&](int ntile, int kc) {
#pragma unroll
        for (int i = 0; i < 4; ++i) {
            const int idx = tid + i * 256;
            pb[i] = *reinterpret_cast<const uint4*>(
                g_cb_bf16 + (size_t)(ntile * 128 + (idx >> 3)) * CD + kc * 64 +
                (idx & 7) * 8);
        }
    };
    auto b_store = [&](int bb) {
        uint32_t* Bs32 = reinterpret_cast<uint32_t*>(smem + SM_BS + bb * BBUF);
#pragma unroll
        for (int i = 0; i < 4; ++i) {
            const int idx = tid + i * 256;
            *reinterpret_cast<uint4*>(&Bs32[(idx >> 3) * B_STRIDE_W + (idx & 7) * 4]) = pb[i];
        }
    };

    // ---- main: 8 N-tiles of 128 codes ----
    for (int ntile = 0; ntile < 8; ++ntile) {
        const int Nb = ntile * 128;

        float acc[4][4][4];
#pragma unroll
        for (int a = 0; a < 4; ++a)
#pragma unroll
            for (int b = 0; b < 4; ++b)
#pragma unroll
                for (int c = 0; c < 4; ++c) acc[a][b][c] = 0.0f;

        b_fetch(ntile, 0);
        b_store(0);                       // prev n-tile's buf0 readers sync'd out
        __syncthreads();

        for (int kc = 0; kc < 8; ++kc) {
            if (kc < 7) b_fetch(ntile, kc + 1);

            const uint32_t bbuf = b_base + (uint32_t)((kc & 1) * BBUF);
#pragma unroll
            for (int s = 0; s < 4; ++s) {
                uint32_t bf[2][4];
                ldsm_x4(bf[0], bbuf + (uint32_t)(((wn * 32 +  0) * B_STRIDE_W + s * 8) * 4) + b_lane_off);
                ldsm_x4(bf[1], bbuf + (uint32_t)(((wn * 32 + 16) * B_STRIDE_W + s * 8) * 4) + b_lane_off);
#pragma unroll
                for (int mt = 0; mt < 4; ++mt) {
                    uint32_t af[4];
                    ldsm_x4(af, a_base +
                        (uint32_t)((((wm * 64 + mt * 16) * A_STRIDE_W) + kc * 32 + s * 8) * 4) +
                        a_lane_off);
                    mma16816(acc[mt][0], af, &bf[0][0]);
                    mma16816(acc[mt][1], af, &bf[0][2]);
                    mma16816(acc[mt][2], af, &bf[1][0]);
                    mma16816(acc[mt][3], af, &bf[1][2]);
                }
            }
            if (kc < 7) {
                b_store((kc + 1) & 1);
                __syncthreads();
            }
        }

        // fold this N-tile into per-lane smem top-4 lists
#pragma unroll
        for (int nt = 0; nt < 4; ++nt) {
            const int c2 = Nb + wn * 32 + nt * 8 + 2 * t4;
            const float h0 = __ldg(&g_half_hat[c2]);
            const float h1 = __ldg(&g_half_hat[c2 + 1]);
#pragma unroll
            for (int mt = 0; mt < 4; ++mt) {
                ins4(tvs, tis, tid, mt * 2,     acc[mt][nt][0] - h0, c2);
                ins4(tvs, tis, tid, mt * 2,     acc[mt][nt][1] - h1, c2 + 1);
                ins4(tvs, tis, tid, mt * 2 + 1, acc[mt][nt][2] - h0, c2);
                ins4(tvs, tis, tid, mt * 2 + 1, acc[mt][nt][3] - h1, c2 + 1);
            }
        }
        __syncthreads();   // fold done before next n-tile's b_store(0)
    }

    float* mv = reinterpret_cast<float*>(smem + SM_MV);   // [row][wn][4]
    int*   mi = reinterpret_cast<int*>(smem + SM_MI);

    // quad merge (lanes t4=0..3 share rows), one lane writes per slot
#pragma unroll
    for (int slot = 0; slot < 8; ++slot) {
        float v4[4]; int i4[4];
#pragma unroll
        for (int j = 0; j < 4; ++j) {
            v4[j] = tvs[(slot * 4 + j) * 256 + tid];
            i4[j] = (int)tis[(slot * 4 + j) * 256 + tid];
        }
#pragma unroll
        for (int off = 1; off <= 2; off <<= 1) {
            float ov[4]; int oi[4];
#pragma unroll
            for (int j = 0; j < 4; ++j) {
                ov[j] = __shfl_xor_sync(0xffffffffu, v4[j], off);
                oi[j] = __shfl_xor_sync(0xffffffffu, i4[j], off);
            }
#pragma unroll
            for (int j = 0; j < 4; ++j) rins4(v4, i4, ov[j], oi[j]);
        }
        if (t4 == 0) {
            const int row = wm * 64 + (slot >> 1) * 16 + g + (slot & 1) * 8;
            const int e = (row * 4 + wn) * 4;
#pragma unroll
            for (int j = 0; j < 4; ++j) { mv[e + j] = v4[j]; mi[e + j] = i4[j]; }
        }
    }
    __syncthreads();

    // final per-row merge of the 4 warp_n lists
    if (tid < 128) {
        float v4[4] = { -INFINITY, -INFINITY, -INFINITY, -INFINITY };
        int   i4[4] = { 0, 0, 0, 0 };
#pragma unroll
        for (int e = 0; e < 16; ++e)
            rins4(v4, i4, mv[tid * 16 + e], mi[tid * 16 + e]);
        const size_t r = (size_t)(r0 + tid);
        *reinterpret_cast<float4*>(&g_scr_v[r * 4]) = make_float4(v4[0], v4[1], v4[2], v4[3]);
        *reinterpret_cast<int4*>(&g_scr_i[r * 4])   = make_int4(i4[0], i4[1], i4[2], i4[3]);
    }
}

// ===========================================================================
// Kernel 3: exact fp32 rescore of screen candidates within margin, then
// gather-write winning codebook row back into [N, C, T].
// ===========================================================================
__global__ __launch_bounds__(128) void vq_rescore_gather_kernel(
    const float* __restrict__ x, const float* __restrict__ cb,
    float* __restrict__ out, long long out_size)
{
    const int r = blockIdx.x * 128 + threadIdx.x;
    const int n = r >> 11;
    const int t = r & (TD - 1);

    const float4 sv = *reinterpret_cast<const float4*>(&g_scr_v[(size_t)r * 4]);
    const int4   si = *reinterpret_cast<const int4*>(&g_scr_i[(size_t)r * 4]);
    const float thr = sv.x - 1.0f;     // margin ~8 sigma of bf16 screen noise

    const float* xp = x + (size_t)n * CD * TD + t;

    float best;
    {
        const float* c0 = cb + (size_t)si.x * CD;
        float a = 0.0f;
#pragma unroll 8
        for (int c = 0; c < CD; ++c)
            a = fmaf(__ldg(xp + (size_t)c * TD), __ldg(c0 + c), a);
        best = a - __ldg(&g_half_exact[si.x]);
    }
    int bidx = si.x;

    const int   cid[3] = { si.y, si.z, si.w };
    const float cvv[3] = { sv.y, sv.z, sv.w };
#pragma unroll
    for (int m = 0; m < 3; ++m) {
        if (cvv[m] >= thr) {
            const float* cm = cb + (size_t)cid[m] * CD;
            float a = 0.0f;
#pragma unroll 8
            for (int c = 0; c < CD; ++c)
                a = fmaf(__ldg(xp + (size_t)c * TD), __ldg(cm + c), a);
            const float s = a - __ldg(&g_half_exact[cid[m]]);
            if (s > best || (s == best && cid[m] < bidx)) { best = s; bidx = cid[m]; }
        }
    }

    const float4* crow = reinterpret_cast<const float4*>(cb + (size_t)bidx * CD);
    float* ob = out + (size_t)n * CD * TD + t;
#pragma unroll 4
    for (int c4 = 0; c4 < CD / 4; ++c4) {
        const float4 w = __ldg(crow + c4);
        ob[(size_t)(c4 * 4 + 0) * TD] = w.x;
        ob[(size_t)(c4 * 4 + 1) * TD] = w.y;
        ob[(size_t)(c4 * 4 + 2) * TD] = w.z;
        ob[(size_t)(c4 * 4 + 3) * TD] = w.w;
    }
    if (r == 0) {
        for (long long e = XD_ELEMS; e < out_size; ++e) out[e] = 0.0f;
    }
}

// ===========================================================================
extern "C" void kernel_launch(void* const* d_in, const int* in_sizes, int n_in,
                              void* d_out, int out_size)
{
    const float* x  = (const float*)d_in[0];
    const float* cb = (const float*)d_in[1];
    if (n_in >= 2 && in_sizes[0] < in_sizes[1]) {
        const float* tmp = x; x = cb; cb = tmp;
    }
    float* out = (float*)d_out;

    cudaFuncSetAttribute(vq_screen_kernel,
                         cudaFuncAttributeMaxDynamicSharedMemorySize, SM_TOTAL);

    vq_prep_kernel<<<KC, 128>>>(cb);
    vq_screen_kernel<<<N_SCREEN_CTAS, 256, SM_TOTAL>>>(x);
    vq_rescore_gather_kernel<<<NT_ROWS / 128, 128>>>(x, cb, out, (long long)out_size);
}